// round 2
// baseline (speedup 1.0000x reference)
#include <cuda_runtime.h>
#include <cstdint>

#define NSTEP 2176
#define BURN  128
#define DIMX  512
#define HID   1024
#define NCTA  32
#define TPB   256

// ---------------- scratch (device globals: no allocation allowed) ----------
__device__ float               g_dx[NSTEP * DIMX];      // scaled noise: normal * 0.1
__device__ float               g_u [NSTEP];             // per-step uniforms
__device__ unsigned long long  g_slots[(NSTEP + 1) * NCTA]; // tagged partials (unique slot per step)

// ---------------- threefry2x32 (JAX-exact) ---------------------------------
__device__ __forceinline__ uint32_t rotl32(uint32_t v, int r) {
    return (v << r) | (v >> (32 - r));
}
__device__ __forceinline__ void tf2x32(uint32_t k0, uint32_t k1,
                                       uint32_t x0, uint32_t x1,
                                       uint32_t& o0, uint32_t& o1) {
    uint32_t k2 = k0 ^ k1 ^ 0x1BD11BDAu;
    x0 += k0; x1 += k1;
#define TF_R(R) { x0 += x1; x1 = rotl32(x1, R); x1 ^= x0; }
    TF_R(13) TF_R(15) TF_R(26) TF_R(6)
    x0 += k1; x1 += k2 + 1u;
    TF_R(17) TF_R(29) TF_R(16) TF_R(24)
    x0 += k2; x1 += k0 + 2u;
    TF_R(13) TF_R(15) TF_R(26) TF_R(6)
    x0 += k0; x1 += k1 + 3u;
    TF_R(17) TF_R(29) TF_R(16) TF_R(24)
    x0 += k1; x1 += k2 + 4u;
    TF_R(13) TF_R(15) TF_R(26) TF_R(6)
    x0 += k2; x1 += k0 + 5u;
#undef TF_R
    o0 = x0; o1 = x1;
}

// partitionable random_bits (32-bit): one call per flat index, XOR outputs
__device__ __forceinline__ uint32_t rbits32(uint32_t k0, uint32_t k1, uint32_t idx) {
    uint32_t o0, o1;
    tf2x32(k0, k1, 0u, idx, o0, o1);
    return o0 ^ o1;
}

// bits -> [0,1) float, JAX style
__device__ __forceinline__ float bits_to_unit(uint32_t b) {
    return __uint_as_float((b >> 9) | 0x3f800000u) - 1.0f;
}

// XLA ErfInv32 (Giles): w = -log1p(-x*x); log1p correctly rounded via double.
__device__ __forceinline__ float erfinv_xla(float x) {
    float xx = x * x;                       // rounded f32 first (as XLA does)
    float w = -(float)log1p(-(double)xx);   // correctly-rounded log1pf
    float p;
    if (w < 5.0f) {
        w = w - 2.5f;
        p = 2.81022636e-08f;
        p = fmaf(p, w, 3.43273939e-07f);
        p = fmaf(p, w, -3.5233877e-06f);
        p = fmaf(p, w, -4.39150654e-06f);
        p = fmaf(p, w, 0.00021858087f);
        p = fmaf(p, w, -0.00125372503f);
        p = fmaf(p, w, -0.00417768164f);
        p = fmaf(p, w, 0.246640727f);
        p = fmaf(p, w, 1.50140941f);
    } else {
        w = __fsqrt_rn(w) - 3.0f;
        p = -0.000200214257f;
        p = fmaf(p, w, 0.000100950558f);
        p = fmaf(p, w, 0.00134934322f);
        p = fmaf(p, w, -0.00367342844f);
        p = fmaf(p, w, 0.00573950773f);
        p = fmaf(p, w, -0.0076224613f);
        p = fmaf(p, w, 0.00943887047f);
        p = fmaf(p, w, 1.00167406f);
        p = fmaf(p, w, 2.83297682f);
    }
    return p * x;
}

// XLA EmitFastTanh f32 (with_fma clamp constant)
__device__ __forceinline__ float tanh_xla(float x) {
    const float kClamp = 7.99881172180175781f;
    float xc = fminf(fmaxf(x, -kClamp), kClamp);
    float x2 = xc * xc;
    float p = fmaf(x2, -2.76076847742355e-16f, 2.00018790482477e-13f);
    p = fmaf(x2, p, -8.60467152213735e-11f);
    p = fmaf(x2, p, 5.12229709037114e-08f);
    p = fmaf(x2, p, 1.48572235717979e-05f);
    p = fmaf(x2, p, 6.37261928875436e-04f);
    p = fmaf(x2, p, 4.89352455891786e-03f);
    p = xc * p;
    float q = fmaf(x2, 1.19825839466702e-06f, 1.18534705686654e-04f);
    q = fmaf(x2, q, 2.26843463243900e-03f);
    q = fmaf(x2, q, 4.89352518554385e-03f);
    float r = __fdiv_rn(p, q);
    return (fabsf(x) < 0.0004f) ? x : r;
}

// ---------------- kernel 1: precompute all noise / uniforms ----------------
// Partitionable threefry derivation:
//   key_t   = tf(0, 1, 0, t)                       (both words; foldlike split)
//   k_noise = tf(key_t, 0, 0)                      (child 0)
//   k_unif  = tf(key_t, 0, 1)                      (child 1)
//   noise bits[i] = o0^o1 of tf(k_noise, 0, i),  i in [0,512)
//   unif  bits    = o0^o1 of tf(k_unif, 0, 0)
__global__ void __launch_bounds__(TPB) noise_kernel() {
    const int t = blockIdx.x;
    const int tid = threadIdx.x;

    uint32_t kt0, kt1;
    tf2x32(0u, 1u, 0u, (uint32_t)t, kt0, kt1);

    uint32_t n0, n1, u0, u1;
    tf2x32(kt0, kt1, 0u, 0u, n0, n1);   // k_noise = (n0, n1)
    tf2x32(kt0, kt1, 0u, 1u, u0, u1);   // k_unif  = (u0, u1)

    const float LO = __uint_as_float(0xBF7FFFFFu);      // nextafter(-1,0)
    const float SQRT2 = __uint_as_float(0x3FB504F3u);   // f32(sqrt(2))
    const float STEP = 0.1f;

#pragma unroll
    for (int h = 0; h < 2; ++h) {
        int i = tid + h * 256;
        uint32_t b = rbits32(n0, n1, (uint32_t)i);
        float f = bits_to_unit(b);
        float u = fmaxf(LO, f * 2.0f + LO);             // (hi-lo) rounds to 2.0f
        float nv = SQRT2 * erfinv_xla(u);
        g_dx[t * DIMX + i] = nv * STEP;
    }

    if (tid == 0) {
        uint32_t b = rbits32(u0, u1, 0u);
        g_u[t] = bits_to_unit(b);                       // minval=0, maxval=1
    }
}

// ---------------- kernel 2: persistent sequential chain --------------------
__global__ void __launch_bounds__(TPB, 1) chain_kernel(
    const float* __restrict__ x0, const float* __restrict__ W1,
    const float* __restrict__ b1, const float* __restrict__ W2,
    const float* __restrict__ b2, float* __restrict__ out)
{
    __shared__ __align__(16) float xbuf[2][DIMX];
    __shared__ float zred[8][32];
    __shared__ float pvals[NCTA];

    const int tid  = threadIdx.x;
    const int c    = blockIdx.x;
    const int lane = tid & 31;
    const int s    = tid >> 5;           // warp id = row segment
    const int j    = c * 32 + lane;      // hidden column owned (per lane)
    const int i0   = tid * 2;

    // W1 slice into registers: rows [s*64, s*64+64), column j
    float w[64];
#pragma unroll
    for (int k = 0; k < 64; ++k) w[k] = W1[(s * 64 + k) * HID + j];

    for (int i = tid; i < DIMX; i += TPB) xbuf[0][i] = x0[i];

    const float b1v = b1[j];
    const float W2v = W2[j];
    const float b2v = b2[0];

    float p_old = 0.0f;
    int cur = 0;
    float dxa = 0.0f, dxb = 0.0f;        // prefetched deltas for next step
    float u_pend = 0.0f;                 // prefetched uniform for next step
    __syncthreads();

    for (int t = -1; t < NSTEP; ++t) {
        int xn = cur;
        if (t >= 0) {
            xn = cur ^ 1;
            xbuf[xn][i0]     = xbuf[cur][i0]     + dxa;
            xbuf[xn][i0 + 1] = xbuf[cur][i0 + 1] + dxb;
        }
        __syncthreads();

        // partial GEMV: acc = sum_i W1[i,j] * x[i] over this warp's 64 rows
        const float4* xv = (const float4*)&xbuf[xn][s * 64];
        float acc = 0.0f;
#pragma unroll
        for (int k = 0; k < 16; ++k) {
            float4 v = xv[k];
            acc = fmaf(w[4 * k + 0], v.x, acc);
            acc = fmaf(w[4 * k + 1], v.y, acc);
            acc = fmaf(w[4 * k + 2], v.z, acc);
            acc = fmaf(w[4 * k + 3], v.w, acc);
        }
        zred[s][lane] = acc;
        __syncthreads();

        // prefetch next step's noise + uniform (overlaps reduce/spin)
        if (t + 1 < NSTEP) {
            dxa = g_dx[(t + 1) * DIMX + i0];
            dxb = g_dx[(t + 1) * DIMX + i0 + 1];
        }
        float u_new = (t + 1 < NSTEP) ? g_u[t + 1] : 0.0f;

        if (s == 0) {
            float z = zred[0][lane];
#pragma unroll
            for (int q = 1; q < 8; ++q) z += zred[q][lane];
            z += b1v;
            float contrib = tanh_xla(z) * W2v;
#pragma unroll
            for (int off = 16; off; off >>= 1)
                contrib += __shfl_xor_sync(0xffffffffu, contrib, off);

            unsigned long long want_tag = (unsigned long long)(unsigned)(t + 2);
            if (lane == 0) {
                unsigned long long pk = (want_tag << 32) |
                                        (unsigned long long)__float_as_uint(contrib);
                asm volatile("st.release.gpu.global.u64 [%0], %1;"
                             :: "l"(&g_slots[(t + 1) * NCTA + c]), "l"(pk) : "memory");
            }
            // fused gather+barrier: poll all 32 CTA slots for this step
            unsigned long long got;
            unsigned long long* slot = &g_slots[(t + 1) * NCTA + lane];
            do {
                asm volatile("ld.acquire.gpu.global.u64 %0, [%1];"
                             : "=l"(got) : "l"(slot));
            } while ((got >> 32) != want_tag);
            pvals[lane] = __uint_as_float((unsigned)got);
        }
        __syncthreads();

        // redundant, bit-identical decision in every CTA / thread
        float S = 0.0f;
#pragma unroll
        for (int q = 0; q < NCTA; ++q) S += pvals[q];
        float m = S + b2v;
        float p_new = m * m;

        if (t < 0) {
            p_old = p_new;                       // psi2(x0)
        } else {
            float ratio = fminf(__fdiv_rn(p_new, p_old + 1e-12f), 1.0f);
            if (u_pend < ratio) { cur = xn; p_old = p_new; }
            if (t >= BURN && (t & (NCTA - 1)) == c) {
                int row = t - BURN;
                out[row * DIMX + i0]     = xbuf[cur][i0];
                out[row * DIMX + i0 + 1] = xbuf[cur][i0 + 1];
            }
        }
        u_pend = u_new;
    }
}

// ---------------- launch ----------------------------------------------------
extern "C" void kernel_launch(void* const* d_in, const int* in_sizes, int n_in,
                              void* d_out, int out_size) {
    const float* x0 = (const float*)d_in[0];
    const float* W1 = (const float*)d_in[1];
    const float* b1 = (const float*)d_in[2];
    const float* W2 = (const float*)d_in[3];
    const float* b2 = (const float*)d_in[4];
    float* out = (float*)d_out;

    noise_kernel<<<NSTEP, TPB>>>();
    chain_kernel<<<NCTA, TPB>>>(x0, W1, b1, W2, b2, out);
}